// round 15
// baseline (speedup 1.0000x reference)
#include <cuda_runtime.h>
#include <cuda_fp16.h>
#include <mma.h>
#include <cstdint>

using namespace nvcuda;

// ---------------------------------------------------------------------------
// GraphSAGE 2-layer forward, fp16 datapath:
//   CSR build: count(+position record) -> 2-kernel parallel scan (tile scan;
//   add-with-inline-sums-scan) -> atomic-free fill. 4-edge-batch HADD2
//   gathers; wmma fp16 GEMM with fp32 accumulate + fp16 weight split.
// N = 100000, E = 1e6, d_in=64, d_hid=128, d_out=64.
// ---------------------------------------------------------------------------

#define N_NODES 100000
#define E_MAX   1000000
#define D_IN    64
#define D_HID   128
#define D_OUT   64
#define SCAN_TILE 1024
#define N_TILES ((N_NODES + SCAN_TILE - 1) / SCAN_TILE)   // 98

// Scratch (device globals; no allocation allowed)
__device__ int    g_cnt   [N_NODES];
__device__ int    g_rowptr[N_NODES + 1];
__device__ int    g_bsum  [128];
__device__ int    g_pos   [E_MAX];             // per-edge within-bucket slot
__device__ int    g_csrsrc[E_MAX];
__device__ __half g_xh    [N_NODES * D_IN];    // fp16 mirror of x
__device__ __half g_h1h   [N_NODES * D_HID];   // fp16 h1 (sole copy)
__device__ __half g_agg1h [N_NODES * D_IN];    // fp16 mean-agg for layer 1
__device__ __half g_agg2h [N_NODES * D_HID];   // fp16 mean-agg for layer 2
__device__ __half g_B1h[128 * 128];            // [K][N] hi(W1) fp16
__device__ __half g_B1l[128 * 128];            // lo(W1)
__device__ __half g_B2h[256 * 64];             // [K][N] hi(W2)
__device__ __half g_B2l[256 * 64];             // lo(W2)

// ===========================================================================
// prep: fp32->fp16 mirror of x  +  zero the count array (one launch)
// ===========================================================================
#define F2H_N4   (N_NODES * D_IN / 4)          // 400k float4
#define ZERO_N4  (N_NODES / 4)                 // 25k int4
__global__ void prep_kernel(const float4* __restrict__ x4,
                            __half2* __restrict__ xh2,
                            int4* __restrict__ cnt4) {
    int i = blockIdx.x * blockDim.x + threadIdx.x;
    if (i < F2H_N4) {
        float4 v = x4[i];
        xh2[i * 2]     = __floats2half2_rn(v.x, v.y);
        xh2[i * 2 + 1] = __floats2half2_rn(v.z, v.w);
    }
    if (i < ZERO_N4) cnt4[i] = make_int4(0, 0, 0, 0);
}

// count + per-edge position record
__global__ void count_kernel(const int2* __restrict__ dst2,
                             int* __restrict__ cnt,
                             int2* __restrict__ pos2, int E2) {
    int e = blockIdx.x * blockDim.x + threadIdx.x;
    if (e < E2) {
        int2 d = dst2[e];
        int p0 = atomicAdd(&cnt[d.x], 1);
        int p1 = atomicAdd(&cnt[d.y], 1);
        pos2[e] = make_int2(p0, p1);
    }
}

// Phase 1: per-tile exclusive scan (coalesced), tile totals to bsum.
__global__ __launch_bounds__(SCAN_TILE)
void scan_local_kernel(const int* __restrict__ cnt,
                       int* __restrict__ local,
                       int* __restrict__ bsum, int n) {
    __shared__ int s[SCAN_TILE];
    const int tid = threadIdx.x;
    const int gid = blockIdx.x * SCAN_TILE + tid;
    int v = (gid < n) ? cnt[gid] : 0;
    s[tid] = v;
    __syncthreads();
    for (int off = 1; off < SCAN_TILE; off <<= 1) {
        int t = 0;
        if (tid >= off) t = s[tid - off];
        __syncthreads();
        if (tid >= off) s[tid] += t;
        __syncthreads();
    }
    if (gid < n) local[gid] = s[tid] - v;          // exclusive within tile
    if (tid == SCAN_TILE - 1) bsum[blockIdx.x] = s[tid];
}

// Phase 2+3 fused: every block redundantly scans the 98 tile totals in smem
// (L2-broadcast; trivial) and applies its tile offset. 128 threads/block;
// 1024 % 128 == 0, so each block lies entirely within one tile.
__global__ __launch_bounds__(128)
void scan_add_kernel(const int* __restrict__ bsum,
                     int* __restrict__ row_ptr, int n, int E) {
    __shared__ int s[128];
    __shared__ int ex[128];
    const int tid = threadIdx.x;
    int v = (tid < N_TILES) ? bsum[tid] : 0;
    s[tid] = v;
    __syncthreads();
    for (int off = 1; off < 128; off <<= 1) {
        int t = 0;
        if (tid >= off) t = s[tid - off];
        __syncthreads();
        if (tid >= off) s[tid] += t;
        __syncthreads();
    }
    ex[tid] = s[tid] - v;                          // exclusive offsets
    __syncthreads();
    const int gid = blockIdx.x * 128 + tid;
    const int tile = blockIdx.x >> 3;              // 8 blocks per 1024-tile
    if (gid < n) row_ptr[gid] += ex[tile];
    if (gid == 0) row_ptr[n] = E;
}

// Atomic-free fill: slot comes from the recorded per-edge position.
__global__ void fill_kernel(const int2* __restrict__ src2,
                            const int2* __restrict__ dst2,
                            const int2* __restrict__ pos2,
                            const int* __restrict__ row_ptr,
                            int* __restrict__ csr, int E2) {
    int e = blockIdx.x * blockDim.x + threadIdx.x;
    if (e < E2) {
        int2 s = src2[e];
        int2 d = dst2[e];
        int2 p = pos2[e];
        csr[row_ptr[d.x] + p.x] = s.x;
        csr[row_ptr[d.y] + p.y] = s.y;
    }
}

// ===========================================================================
// Gather + mean over fp16 features (trailing blocks run weight prep).
// 4-edge batches: 4 feature loads in flight; pairwise HADD2 then fp32 acc
// (numerically identical to the pair loop). TPN threads per node.
// ===========================================================================
__device__ __forceinline__ void wprep_item(const float* ws, const float* wn,
                                           __half* Bh, __half* Bl,
                                           int DK2, int NOUT, int i) {
    int k = i / NOUT, n = i % NOUT;
    float w = (k < DK2 / 2) ? ws[k * NOUT + n] : wn[(k - DK2 / 2) * NOUT + n];
    __half hi = __float2half_rn(w);
    Bh[i] = hi;
    Bl[i] = __float2half_rn(w - __half2float(hi));
}

__device__ __forceinline__ void acc_pair_h(float* acc, const uint4& r0, const uint4& r1) {
    const __half2* p0 = reinterpret_cast<const __half2*>(&r0);
    const __half2* p1 = reinterpret_cast<const __half2*>(&r1);
#pragma unroll
    for (int q = 0; q < 4; q++) {
        __half2 hs = __hadd2(p0[q], p1[q]);
        float2 f = __half22float2(hs);
        acc[2 * q]     += f.x;
        acc[2 * q + 1] += f.y;
    }
}
__device__ __forceinline__ void acc_one_h(float* acc, const uint4& r) {
    const __half2* ph = reinterpret_cast<const __half2*>(&r);
#pragma unroll
    for (int q = 0; q < 4; q++) {
        float2 f = __half22float2(ph[q]);
        acc[2 * q]     += f.x;
        acc[2 * q + 1] += f.y;
    }
}

template <int TPN, bool WPREP>
__global__ __launch_bounds__(256)
void gather_h_kernel(const uint4* __restrict__ feat,
                     const int* __restrict__ csr,
                     const int* __restrict__ row_ptr,
                     uint4* __restrict__ aggmean_h, int n,
                     int nGatherBlocks,
                     const float* __restrict__ ws1, const float* __restrict__ wn1,
                     __half* __restrict__ B1h, __half* __restrict__ B1l,
                     const float* __restrict__ ws2, const float* __restrict__ wn2,
                     __half* __restrict__ B2h, __half* __restrict__ B2l) {
    const int tid = threadIdx.x;
    if (WPREP && blockIdx.x >= nGatherBlocks) {
        int b = blockIdx.x - nGatherBlocks;
        int i = b * 256 + tid;
        if (i < 128 * 128) wprep_item(ws1, wn1, B1h, B1l, 128, 128, i);
        if (i < 256 * 64)  wprep_item(ws2, wn2, B2h, B2l, 256, 64, i);
        return;
    }
    const int node = blockIdx.x * (256 / TPN) + tid / TPN;
    const int c = tid % TPN;
    if (node >= n) return;
    const int b = row_ptr[node];
    const int e = row_ptr[node + 1];
    float acc[8];
#pragma unroll
    for (int q = 0; q < 8; q++) acc[q] = 0.f;

    int i = b;
    for (; i + 3 < e; i += 4) {
        int s0 = __ldg(&csr[i]);
        int s1 = __ldg(&csr[i + 1]);
        int s2 = __ldg(&csr[i + 2]);
        int s3 = __ldg(&csr[i + 3]);
        uint4 r0 = __ldg(&feat[(size_t)s0 * TPN + c]);
        uint4 r1 = __ldg(&feat[(size_t)s1 * TPN + c]);
        uint4 r2 = __ldg(&feat[(size_t)s2 * TPN + c]);
        uint4 r3 = __ldg(&feat[(size_t)s3 * TPN + c]);
        acc_pair_h(acc, r0, r1);
        acc_pair_h(acc, r2, r3);
    }
    if (i + 1 < e) {
        int s0 = __ldg(&csr[i]);
        int s1 = __ldg(&csr[i + 1]);
        uint4 r0 = __ldg(&feat[(size_t)s0 * TPN + c]);
        uint4 r1 = __ldg(&feat[(size_t)s1 * TPN + c]);
        acc_pair_h(acc, r0, r1);
        i += 2;
    }
    if (i < e) {
        int s = __ldg(&csr[i]);
        uint4 r = __ldg(&feat[(size_t)s * TPN + c]);
        acc_one_h(acc, r);
    }

    int d = e - b;
    float inv = 1.0f / (float)(d > 1 ? d : 1);
    __half2 h0 = __floats2half2_rn(acc[0] * inv, acc[1] * inv);
    __half2 h1 = __floats2half2_rn(acc[2] * inv, acc[3] * inv);
    __half2 h2 = __floats2half2_rn(acc[4] * inv, acc[5] * inv);
    __half2 h3 = __floats2half2_rn(acc[6] * inv, acc[7] * inv);
    aggmean_h[(size_t)node * TPN + c] = make_uint4(
        *(uint32_t*)&h0, *(uint32_t*)&h1, *(uint32_t*)&h2, *(uint32_t*)&h3);
}

// ===========================================================================
// Layer via wmma fp16 GEMM with weight hi/lo compensation.
// CTA = 128 nodes x NOUT, 8 warps. Warp tile (WROWS*16) x (WCOLS*16).
// LAYER==1: self = xh,  agg = agg1h. Output: fp16 h1h.
// LAYER==2: self = h1h, agg = agg2h. Output: fp32 d_out.
// ===========================================================================
template <int NOUT, int WROWS, int WCOLS, int NCHUNK, int LAYER, bool RELU, bool HALF_OUT>
__global__ __launch_bounds__(256)
void wmma_layer_kernel(const __half* __restrict__ selfh,
                       const __half* __restrict__ aggh,
                       const __half* __restrict__ Bh,
                       const __half* __restrict__ Bl,
                       const float* __restrict__ bias,
                       float* __restrict__ out,
                       __half* __restrict__ outh, int nNodes) {
    constexpr int ROWU4 = (LAYER == 1) ? 8 : 16;  // fp16 source row in uint4
    constexpr int ASTR  = 72;                     // smem A row stride (halfs)
    constexpr int BSTR  = NOUT + 8;               // smem B row stride (halfs)
    constexpr int COLG  = NOUT / (WCOLS * 16);    // warp col groups

    extern __shared__ __align__(32) char smem_raw[];
    __half* sA  = (__half*)smem_raw;                 // 128 x ASTR
    __half* sBh = sA + 128 * ASTR;                   // 64 x BSTR
    __half* sBl = sBh + 64 * BSTR;                   // 64 x BSTR
    float*  sBias = (float*)(sBl + 64 * BSTR);       // 2048 floats

    const int tid = threadIdx.x;
    const int wid = tid >> 5;
    const int lane = tid & 31;
    const int rowg = wid / COLG;
    const int colg = wid % COLG;
    const int base = blockIdx.x * 128;

    for (int i = tid; i < 16 * NOUT; i += 256) sBias[i] = bias[i % NOUT];
    __syncthreads();

    wmma::fragment<wmma::accumulator, 16, 16, 16, float> acc[WROWS][WCOLS];
#pragma unroll
    for (int r = 0; r < WROWS; r++)
#pragma unroll
        for (int c = 0; c < WCOLS; c++)
            wmma::load_matrix_sync(acc[r][c],
                sBias + (colg * WCOLS + c) * 16, NOUT, wmma::mem_row_major);

    for (int kc = 0; kc < NCHUNK; kc++) {
        __syncthreads();

        // ---- stage A: straight fp16 copy, 128 rows x 64 cols ----
        const uint4* src4;
        int qoff;
        if (LAYER == 1) {
            src4 = reinterpret_cast<const uint4*>(kc ? aggh : selfh);
            qoff = 0;
        } else {
            src4 = reinterpret_cast<const uint4*>((kc < 2) ? selfh : aggh);
            qoff = (kc & 1) * 8;
        }
#pragma unroll
        for (int jj = tid; jj < 1024; jj += 256) {
            int m = jj >> 3, c8 = jj & 7;
            int node = base + m;
            uint4 v = make_uint4(0, 0, 0, 0);
            if (node < nNodes)
                v = src4[(size_t)node * ROWU4 + qoff + c8];
            *reinterpret_cast<uint4*>(&sA[m * ASTR + c8 * 8]) = v;
        }
        // ---- stage B: 64 x NOUT fp16 hi/lo ----
#pragma unroll
        for (int jj = tid; jj < 64 * NOUT / 8; jj += 256) {
            int r = jj / (NOUT / 8), c8 = jj % (NOUT / 8);
            size_t g = (size_t)(kc * 64 + r) * NOUT + c8 * 8;
            *reinterpret_cast<uint4*>(&sBh[r * BSTR + c8 * 8]) =
                *reinterpret_cast<const uint4*>(&Bh[g]);
            *reinterpret_cast<uint4*>(&sBl[r * BSTR + c8 * 8]) =
                *reinterpret_cast<const uint4*>(&Bl[g]);
        }
        __syncthreads();

        // ---- MMA over 4 k-steps of 16 ----
#pragma unroll
        for (int kk = 0; kk < 4; kk++) {
            wmma::fragment<wmma::matrix_a, 16, 16, 16, __half, wmma::row_major> a[WROWS];
#pragma unroll
            for (int r = 0; r < WROWS; r++) {
                int rr = (rowg * WROWS + r) * 16;
                wmma::load_matrix_sync(a[r], sA + rr * ASTR + kk * 16, ASTR);
            }
#pragma unroll
            for (int c = 0; c < WCOLS; c++) {
                wmma::fragment<wmma::matrix_b, 16, 16, 16, __half, wmma::row_major> bh, bl;
                int cc = (colg * WCOLS + c) * 16;
                wmma::load_matrix_sync(bh, sBh + kk * 16 * BSTR + cc, BSTR);
                wmma::load_matrix_sync(bl, sBl + kk * 16 * BSTR + cc, BSTR);
#pragma unroll
                for (int r = 0; r < WROWS; r++) {
                    wmma::mma_sync(acc[r][c], a[r], bh, acc[r][c]);
                    wmma::mma_sync(acc[r][c], a[r], bl, acc[r][c]);
                }
            }
        }
    }

    // ---- epilogue ----
    float* scratch = sBias + wid * 256;   // per-warp 16x16 fp32 tile
#pragma unroll
    for (int r = 0; r < WROWS; r++) {
        int rbase = base + (rowg * WROWS + r) * 16;
        if (rbase < nNodes) {
#pragma unroll
            for (int c = 0; c < WCOLS; c++) {
                if (RELU) {
#pragma unroll
                    for (int i = 0; i < acc[r][c].num_elements; i++)
                        acc[r][c].x[i] = fmaxf(acc[r][c].x[i], 0.f);
                }
                int cc = (colg * WCOLS + c) * 16;
                if (HALF_OUT) {
                    __syncwarp();
                    wmma::store_matrix_sync(scratch, acc[r][c], 16,
                                            wmma::mem_row_major);
                    __syncwarp();
                    int lr = lane >> 1, lc = (lane & 1) * 8;
                    float4 va = *reinterpret_cast<float4*>(&scratch[lr * 16 + lc]);
                    float4 vb = *reinterpret_cast<float4*>(&scratch[lr * 16 + lc + 4]);
                    __half2 h0 = __floats2half2_rn(va.x, va.y);
                    __half2 h1 = __floats2half2_rn(va.z, va.w);
                    __half2 h2 = __floats2half2_rn(vb.x, vb.y);
                    __half2 h3 = __floats2half2_rn(vb.z, vb.w);
                    uint4 packed = make_uint4(
                        *(uint32_t*)&h0, *(uint32_t*)&h1,
                        *(uint32_t*)&h2, *(uint32_t*)&h3);
                    *reinterpret_cast<uint4*>(
                        &outh[(size_t)(rbase + lr) * NOUT + cc + lc]) = packed;
                } else {
                    wmma::store_matrix_sync(
                        out + (size_t)rbase * NOUT + cc,
                        acc[r][c], NOUT, wmma::mem_row_major);
                }
            }
        }
    }
}

// ===========================================================================
extern "C" void kernel_launch(void* const* d_in, const int* in_sizes, int n_in,
                              void* d_out, int out_size) {
    const float* x        = (const float*)d_in[0];
    const int*   src      = (const int*)d_in[1];
    const int*   dst      = (const int*)d_in[2];
    const float* w_self1  = (const float*)d_in[3];
    const float* w_neigh1 = (const float*)d_in[4];
    const float* b1       = (const float*)d_in[5];
    const float* w_self2  = (const float*)d_in[6];
    const float* w_neigh2 = (const float*)d_in[7];
    const float* b2       = (const float*)d_in[8];
    float* out = (float*)d_out;

    const int E = in_sizes[1];

    int *cnt, *rowptr, *bsum, *pos, *csrsrc;
    __half *xh, *h1h, *agg1h, *agg2h;
    __half *B1h, *B1l, *B2h, *B2l;
    cudaGetSymbolAddress((void**)&cnt,    g_cnt);
    cudaGetSymbolAddress((void**)&rowptr, g_rowptr);
    cudaGetSymbolAddress((void**)&bsum,   g_bsum);
    cudaGetSymbolAddress((void**)&pos,    g_pos);
    cudaGetSymbolAddress((void**)&csrsrc, g_csrsrc);
    cudaGetSymbolAddress((void**)&xh,     g_xh);
    cudaGetSymbolAddress((void**)&h1h,    g_h1h);
    cudaGetSymbolAddress((void**)&agg1h,  g_agg1h);
    cudaGetSymbolAddress((void**)&agg2h,  g_agg2h);
    cudaGetSymbolAddress((void**)&B1h,    g_B1h);
    cudaGetSymbolAddress((void**)&B1l,    g_B1l);
    cudaGetSymbolAddress((void**)&B2h,    g_B2h);
    cudaGetSymbolAddress((void**)&B2l,    g_B2l);

    constexpr int SMEM_L1 = 128 * 72 * 2 + 2 * 64 * (128 + 8) * 2 + 2048 * 4; // 61440
    constexpr int SMEM_L2 = 128 * 72 * 2 + 2 * 64 * (64 + 8) * 2 + 2048 * 4;  // 45056
    cudaFuncSetAttribute((const void*)wmma_layer_kernel<D_HID, 2, 4, 2, 1, true, true>,
                         cudaFuncAttributeMaxDynamicSharedMemorySize, SMEM_L1);
    cudaFuncSetAttribute((const void*)wmma_layer_kernel<D_OUT, 1, 4, 4, 2, false, false>,
                         cudaFuncAttributeMaxDynamicSharedMemorySize, SMEM_L2);

    const int nTiles = (N_NODES + 127) / 128;
    const int E2 = E / 2;   // E is even (1e6)

    // 1) prep: f2h + zero cnt
    prep_kernel<<<(F2H_N4 + 255) / 256, 256>>>(
        (const float4*)x, (__half2*)xh, (int4*)cnt);

    // 2) count (+ per-edge positions)
    count_kernel<<<(E2 + 255) / 256, 256>>>(
        (const int2*)dst, cnt, (int2*)pos, E2);

    // 3) tile-local scan
    scan_local_kernel<<<N_TILES, SCAN_TILE>>>(cnt, rowptr, bsum, N_NODES);

    // 4) fused sums-scan + offset add (profiled slot)
    scan_add_kernel<<<(N_NODES + 127) / 128, 128>>>(bsum, rowptr, N_NODES, E);

    // 5) atomic-free fill
    fill_kernel<<<(E2 + 255) / 256, 256>>>(
        (const int2*)src, (const int2*)dst, (const int2*)pos, rowptr, csrsrc, E2);

    // 6) gather1 + weight prep (trailing 64 blocks)
    {
        const int gb = (N_NODES * (D_IN / 8) + 255) / 256;   // 3125
        const int wb = (128 * 128 + 255) / 256;              // 64
        gather_h_kernel<D_IN / 8, true><<<gb + wb, 256>>>(
            (const uint4*)xh, csrsrc, rowptr, (uint4*)agg1h, N_NODES, gb,
            w_self1, w_neigh1, B1h, B1l, w_self2, w_neigh2, B2h, B2l);
    }

    // 7) layer 1
    wmma_layer_kernel<D_HID, 2, 4, 2, 1, true, true><<<nTiles, 256, SMEM_L1>>>(
        xh, agg1h, B1h, B1l, b1, nullptr, h1h, N_NODES);

    // 8) gather 2
    gather_h_kernel<D_HID / 8, false><<<(N_NODES * (D_HID / 8) + 255) / 256, 256>>>(
        (const uint4*)h1h, csrsrc, rowptr, (uint4*)agg2h, N_NODES, 1 << 30,
        nullptr, nullptr, nullptr, nullptr, nullptr, nullptr, nullptr, nullptr);

    // 9) layer 2
    wmma_layer_kernel<D_OUT, 1, 4, 4, 2, false, false><<<nTiles, 256, SMEM_L2>>>(
        h1h, agg2h, B2h, B2l, b2, out, nullptr, N_NODES);
}

// round 16
// speedup vs baseline: 1.0460x; 1.0460x over previous
#include <cuda_runtime.h>
#include <cuda_fp16.h>
#include <mma.h>
#include <cstdint>

using namespace nvcuda;

// ---------------------------------------------------------------------------
// GraphSAGE 2-layer forward, fp16 datapath:
//   CSR build: int4 count(+position record) -> tile scan -> fused sums-scan+
//   offset add -> atomic-free int4 fill. HADD2 pair gathers (R14-proven);
//   wmma fp16 GEMM with fp32 accumulate + fp16 weight split (W = Wh + Wl).
// N = 100000, E = 1e6, d_in=64, d_hid=128, d_out=64.
// ---------------------------------------------------------------------------

#define N_NODES 100000
#define E_MAX   1000000
#define D_IN    64
#define D_HID   128
#define D_OUT   64
#define SCAN_TILE 1024
#define N_TILES ((N_NODES + SCAN_TILE - 1) / SCAN_TILE)   // 98

// Scratch (device globals; no allocation allowed)
__device__ int    g_cnt   [N_NODES];
__device__ int    g_rowptr[N_NODES + 1];
__device__ int    g_bsum  [128];
__device__ int    g_pos   [E_MAX];             // per-edge within-bucket slot
__device__ int    g_csrsrc[E_MAX];
__device__ __half g_xh    [N_NODES * D_IN];    // fp16 mirror of x
__device__ __half g_h1h   [N_NODES * D_HID];   // fp16 h1 (sole copy)
__device__ __half g_agg1h [N_NODES * D_IN];    // fp16 mean-agg for layer 1
__device__ __half g_agg2h [N_NODES * D_HID];   // fp16 mean-agg for layer 2
__device__ __half g_B1h[128 * 128];            // [K][N] hi(W1) fp16
__device__ __half g_B1l[128 * 128];            // lo(W1)
__device__ __half g_B2h[256 * 64];             // [K][N] hi(W2)
__device__ __half g_B2l[256 * 64];             // lo(W2)

// ===========================================================================
// prep: fp32->fp16 mirror of x  +  zero the count array (one launch)
// ===========================================================================
#define F2H_N4   (N_NODES * D_IN / 4)          // 400k float4
#define ZERO_N4  (N_NODES / 4)                 // 25k int4
__global__ void prep_kernel(const float4* __restrict__ x4,
                            __half2* __restrict__ xh2,
                            int4* __restrict__ cnt4) {
    int i = blockIdx.x * blockDim.x + threadIdx.x;
    if (i < F2H_N4) {
        float4 v = x4[i];
        xh2[i * 2]     = __floats2half2_rn(v.x, v.y);
        xh2[i * 2 + 1] = __floats2half2_rn(v.z, v.w);
    }
    if (i < ZERO_N4) cnt4[i] = make_int4(0, 0, 0, 0);
}

// count + per-edge position record (4 edges per thread, int4 loads)
__global__ void count_kernel(const int4* __restrict__ dst4,
                             int* __restrict__ cnt,
                             int4* __restrict__ pos4, int E4) {
    int e = blockIdx.x * blockDim.x + threadIdx.x;
    if (e < E4) {
        int4 d = dst4[e];
        int4 p;
        p.x = atomicAdd(&cnt[d.x], 1);
        p.y = atomicAdd(&cnt[d.y], 1);
        p.z = atomicAdd(&cnt[d.z], 1);
        p.w = atomicAdd(&cnt[d.w], 1);
        pos4[e] = p;
    }
}

// Phase 1: per-tile exclusive scan (coalesced), tile totals to bsum.
__global__ __launch_bounds__(SCAN_TILE)
void scan_local_kernel(const int* __restrict__ cnt,
                       int* __restrict__ local,
                       int* __restrict__ bsum, int n) {
    __shared__ int s[SCAN_TILE];
    const int tid = threadIdx.x;
    const int gid = blockIdx.x * SCAN_TILE + tid;
    int v = (gid < n) ? cnt[gid] : 0;
    s[tid] = v;
    __syncthreads();
    for (int off = 1; off < SCAN_TILE; off <<= 1) {
        int t = 0;
        if (tid >= off) t = s[tid - off];
        __syncthreads();
        if (tid >= off) s[tid] += t;
        __syncthreads();
    }
    if (gid < n) local[gid] = s[tid] - v;          // exclusive within tile
    if (tid == SCAN_TILE - 1) bsum[blockIdx.x] = s[tid];
}

// Phase 2+3 fused: every block redundantly scans the 98 tile totals in smem
// (L2-broadcast) and applies its tile offset. 128 threads/block.
__global__ __launch_bounds__(128)
void scan_add_kernel(const int* __restrict__ bsum,
                     int* __restrict__ row_ptr, int n, int E) {
    __shared__ int s[128];
    __shared__ int ex[128];
    const int tid = threadIdx.x;
    int v = (tid < N_TILES) ? bsum[tid] : 0;
    s[tid] = v;
    __syncthreads();
    for (int off = 1; off < 128; off <<= 1) {
        int t = 0;
        if (tid >= off) t = s[tid - off];
        __syncthreads();
        if (tid >= off) s[tid] += t;
        __syncthreads();
    }
    ex[tid] = s[tid] - v;                          // exclusive offsets
    __syncthreads();
    const int gid = blockIdx.x * 128 + tid;
    const int tile = blockIdx.x >> 3;              // 8 blocks per 1024-tile
    if (gid < n) row_ptr[gid] += ex[tile];
    if (gid == 0) row_ptr[n] = E;
}

// Atomic-free fill: slot comes from the recorded per-edge position.
__global__ void fill_kernel(const int4* __restrict__ src4,
                            const int4* __restrict__ dst4,
                            const int4* __restrict__ pos4,
                            const int* __restrict__ row_ptr,
                            int* __restrict__ csr, int E4) {
    int e = blockIdx.x * blockDim.x + threadIdx.x;
    if (e < E4) {
        int4 s = src4[e];
        int4 d = dst4[e];
        int4 p = pos4[e];
        csr[row_ptr[d.x] + p.x] = s.x;
        csr[row_ptr[d.y] + p.y] = s.y;
        csr[row_ptr[d.z] + p.z] = s.z;
        csr[row_ptr[d.w] + p.w] = s.w;
    }
}

// ===========================================================================
// Gather + mean over fp16 features (trailing blocks run weight prep).
// Edge pairs summed via HADD2, accumulated fp32 (R14-proven pair loop).
// TPN threads per node; one LDG.128 per thread per edge.
// ===========================================================================
__device__ __forceinline__ void wprep_item(const float* ws, const float* wn,
                                           __half* Bh, __half* Bl,
                                           int DK2, int NOUT, int i) {
    int k = i / NOUT, n = i % NOUT;
    float w = (k < DK2 / 2) ? ws[k * NOUT + n] : wn[(k - DK2 / 2) * NOUT + n];
    __half hi = __float2half_rn(w);
    Bh[i] = hi;
    Bl[i] = __float2half_rn(w - __half2float(hi));
}

template <int TPN, bool WPREP>
__global__ __launch_bounds__(256)
void gather_h_kernel(const uint4* __restrict__ feat,
                     const int* __restrict__ csr,
                     const int* __restrict__ row_ptr,
                     uint4* __restrict__ aggmean_h, int n,
                     int nGatherBlocks,
                     const float* __restrict__ ws1, const float* __restrict__ wn1,
                     __half* __restrict__ B1h, __half* __restrict__ B1l,
                     const float* __restrict__ ws2, const float* __restrict__ wn2,
                     __half* __restrict__ B2h, __half* __restrict__ B2l) {
    const int tid = threadIdx.x;
    if (WPREP && blockIdx.x >= nGatherBlocks) {
        int b = blockIdx.x - nGatherBlocks;
        int i = b * 256 + tid;
        if (i < 128 * 128) wprep_item(ws1, wn1, B1h, B1l, 128, 128, i);
        if (i < 256 * 64)  wprep_item(ws2, wn2, B2h, B2l, 256, 64, i);
        return;
    }
    const int node = blockIdx.x * (256 / TPN) + tid / TPN;
    const int c = tid % TPN;
    if (node >= n) return;
    const int b = row_ptr[node];
    const int e = row_ptr[node + 1];
    float acc[8];
#pragma unroll
    for (int q = 0; q < 8; q++) acc[q] = 0.f;

    int i = b;
#pragma unroll 2
    for (; i + 1 < e; i += 2) {
        int s0 = __ldg(&csr[i]);
        int s1 = __ldg(&csr[i + 1]);
        uint4 r0 = __ldg(&feat[(size_t)s0 * TPN + c]);
        uint4 r1 = __ldg(&feat[(size_t)s1 * TPN + c]);
        const __half2* p0 = reinterpret_cast<const __half2*>(&r0);
        const __half2* p1 = reinterpret_cast<const __half2*>(&r1);
#pragma unroll
        for (int q = 0; q < 4; q++) {
            __half2 hs = __hadd2(p0[q], p1[q]);
            float2 f = __half22float2(hs);
            acc[2 * q]     += f.x;
            acc[2 * q + 1] += f.y;
        }
    }
    if (i < e) {
        int s = __ldg(&csr[i]);
        uint4 r = __ldg(&feat[(size_t)s * TPN + c]);
        const __half2* ph = reinterpret_cast<const __half2*>(&r);
#pragma unroll
        for (int q = 0; q < 4; q++) {
            float2 f = __half22float2(ph[q]);
            acc[2 * q]     += f.x;
            acc[2 * q + 1] += f.y;
        }
    }

    int d = e - b;
    float inv = 1.0f / (float)(d > 1 ? d : 1);
    __half2 h0 = __floats2half2_rn(acc[0] * inv, acc[1] * inv);
    __half2 h1 = __floats2half2_rn(acc[2] * inv, acc[3] * inv);
    __half2 h2 = __floats2half2_rn(acc[4] * inv, acc[5] * inv);
    __half2 h3 = __floats2half2_rn(acc[6] * inv, acc[7] * inv);
    aggmean_h[(size_t)node * TPN + c] = make_uint4(
        *(uint32_t*)&h0, *(uint32_t*)&h1, *(uint32_t*)&h2, *(uint32_t*)&h3);
}

// ===========================================================================
// Layer via wmma fp16 GEMM with weight hi/lo compensation.
// CTA = 128 nodes x NOUT, 8 warps. Warp tile (WROWS*16) x (WCOLS*16).
// LAYER==1: self = xh,  agg = agg1h. Output: fp16 h1h.
// LAYER==2: self = h1h, agg = agg2h. Output: fp32 d_out.
// ===========================================================================
template <int NOUT, int WROWS, int WCOLS, int NCHUNK, int LAYER, bool RELU, bool HALF_OUT>
__global__ __launch_bounds__(256)
void wmma_layer_kernel(const __half* __restrict__ selfh,
                       const __half* __restrict__ aggh,
                       const __half* __restrict__ Bh,
                       const __half* __restrict__ Bl,
                       const float* __restrict__ bias,
                       float* __restrict__ out,
                       __half* __restrict__ outh, int nNodes) {
    constexpr int ROWU4 = (LAYER == 1) ? 8 : 16;  // fp16 source row in uint4
    constexpr int ASTR  = 72;                     // smem A row stride (halfs)
    constexpr int BSTR  = NOUT + 8;               // smem B row stride (halfs)
    constexpr int COLG  = NOUT / (WCOLS * 16);    // warp col groups

    extern __shared__ __align__(32) char smem_raw[];
    __half* sA  = (__half*)smem_raw;                 // 128 x ASTR
    __half* sBh = sA + 128 * ASTR;                   // 64 x BSTR
    __half* sBl = sBh + 64 * BSTR;                   // 64 x BSTR
    float*  sBias = (float*)(sBl + 64 * BSTR);       // 2048 floats

    const int tid = threadIdx.x;
    const int wid = tid >> 5;
    const int lane = tid & 31;
    const int rowg = wid / COLG;
    const int colg = wid % COLG;
    const int base = blockIdx.x * 128;

    for (int i = tid; i < 16 * NOUT; i += 256) sBias[i] = bias[i % NOUT];
    __syncthreads();

    wmma::fragment<wmma::accumulator, 16, 16, 16, float> acc[WROWS][WCOLS];
#pragma unroll
    for (int r = 0; r < WROWS; r++)
#pragma unroll
        for (int c = 0; c < WCOLS; c++)
            wmma::load_matrix_sync(acc[r][c],
                sBias + (colg * WCOLS + c) * 16, NOUT, wmma::mem_row_major);

    for (int kc = 0; kc < NCHUNK; kc++) {
        __syncthreads();

        // ---- stage A: straight fp16 copy, 128 rows x 64 cols ----
        const uint4* src4;
        int qoff;
        if (LAYER == 1) {
            src4 = reinterpret_cast<const uint4*>(kc ? aggh : selfh);
            qoff = 0;
        } else {
            src4 = reinterpret_cast<const uint4*>((kc < 2) ? selfh : aggh);
            qoff = (kc & 1) * 8;
        }
#pragma unroll
        for (int jj = tid; jj < 1024; jj += 256) {
            int m = jj >> 3, c8 = jj & 7;
            int node = base + m;
            uint4 v = make_uint4(0, 0, 0, 0);
            if (node < nNodes)
                v = src4[(size_t)node * ROWU4 + qoff + c8];
            *reinterpret_cast<uint4*>(&sA[m * ASTR + c8 * 8]) = v;
        }
        // ---- stage B: 64 x NOUT fp16 hi/lo ----
#pragma unroll
        for (int jj = tid; jj < 64 * NOUT / 8; jj += 256) {
            int r = jj / (NOUT / 8), c8 = jj % (NOUT / 8);
            size_t g = (size_t)(kc * 64 + r) * NOUT + c8 * 8;
            *reinterpret_cast<uint4*>(&sBh[r * BSTR + c8 * 8]) =
                *reinterpret_cast<const uint4*>(&Bh[g]);
            *reinterpret_cast<uint4*>(&sBl[r * BSTR + c8 * 8]) =
                *reinterpret_cast<const uint4*>(&Bl[g]);
        }
        __syncthreads();

        // ---- MMA over 4 k-steps of 16 ----
#pragma unroll
        for (int kk = 0; kk < 4; kk++) {
            wmma::fragment<wmma::matrix_a, 16, 16, 16, __half, wmma::row_major> a[WROWS];
#pragma unroll
            for (int r = 0; r < WROWS; r++) {
                int rr = (rowg * WROWS + r) * 16;
                wmma::load_matrix_sync(a[r], sA + rr * ASTR + kk * 16, ASTR);
            }
#pragma unroll
            for (int c = 0; c < WCOLS; c++) {
                wmma::fragment<wmma::matrix_b, 16, 16, 16, __half, wmma::row_major> bh, bl;
                int cc = (colg * WCOLS + c) * 16;
                wmma::load_matrix_sync(bh, sBh + kk * 16 * BSTR + cc, BSTR);
                wmma::load_matrix_sync(bl, sBl + kk * 16 * BSTR + cc, BSTR);
#pragma unroll
                for (int r = 0; r < WROWS; r++) {
                    wmma::mma_sync(acc[r][c], a[r], bh, acc[r][c]);
                    wmma::mma_sync(acc[r][c], a[r], bl, acc[r][c]);
                }
            }
        }
    }

    // ---- epilogue ----
    float* scratch = sBias + wid * 256;   // per-warp 16x16 fp32 tile
#pragma unroll
    for (int r = 0; r < WROWS; r++) {
        int rbase = base + (rowg * WROWS + r) * 16;
        if (rbase < nNodes) {
#pragma unroll
            for (int c = 0; c < WCOLS; c++) {
                if (RELU) {
#pragma unroll
                    for (int i = 0; i < acc[r][c].num_elements; i++)
                        acc[r][c].x[i] = fmaxf(acc[r][c].x[i], 0.f);
                }
                int cc = (colg * WCOLS + c) * 16;
                if (HALF_OUT) {
                    __syncwarp();
                    wmma::store_matrix_sync(scratch, acc[r][c], 16,
                                            wmma::mem_row_major);
                    __syncwarp();
                    int lr = lane >> 1, lc = (lane & 1) * 8;
                    float4 va = *reinterpret_cast<float4*>(&scratch[lr * 16 + lc]);
                    float4 vb = *reinterpret_cast<float4*>(&scratch[lr * 16 + lc + 4]);
                    __half2 h0 = __floats2half2_rn(va.x, va.y);
                    __half2 h1 = __floats2half2_rn(va.z, va.w);
                    __half2 h2 = __floats2half2_rn(vb.x, vb.y);
                    __half2 h3 = __floats2half2_rn(vb.z, vb.w);
                    uint4 packed = make_uint4(
                        *(uint32_t*)&h0, *(uint32_t*)&h1,
                        *(uint32_t*)&h2, *(uint32_t*)&h3);
                    *reinterpret_cast<uint4*>(
                        &outh[(size_t)(rbase + lr) * NOUT + cc + lc]) = packed;
                } else {
                    wmma::store_matrix_sync(
                        out + (size_t)rbase * NOUT + cc,
                        acc[r][c], NOUT, wmma::mem_row_major);
                }
            }
        }
    }
}

// ===========================================================================
extern "C" void kernel_launch(void* const* d_in, const int* in_sizes, int n_in,
                              void* d_out, int out_size) {
    const float* x        = (const float*)d_in[0];
    const int*   src      = (const int*)d_in[1];
    const int*   dst      = (const int*)d_in[2];
    const float* w_self1  = (const float*)d_in[3];
    const float* w_neigh1 = (const float*)d_in[4];
    const float* b1       = (const float*)d_in[5];
    const float* w_self2  = (const float*)d_in[6];
    const float* w_neigh2 = (const float*)d_in[7];
    const float* b2       = (const float*)d_in[8];
    float* out = (float*)d_out;

    const int E = in_sizes[1];

    int *cnt, *rowptr, *bsum, *pos, *csrsrc;
    __half *xh, *h1h, *agg1h, *agg2h;
    __half *B1h, *B1l, *B2h, *B2l;
    cudaGetSymbolAddress((void**)&cnt,    g_cnt);
    cudaGetSymbolAddress((void**)&rowptr, g_rowptr);
    cudaGetSymbolAddress((void**)&bsum,   g_bsum);
    cudaGetSymbolAddress((void**)&pos,    g_pos);
    cudaGetSymbolAddress((void**)&csrsrc, g_csrsrc);
    cudaGetSymbolAddress((void**)&xh,     g_xh);
    cudaGetSymbolAddress((void**)&h1h,    g_h1h);
    cudaGetSymbolAddress((void**)&agg1h,  g_agg1h);
    cudaGetSymbolAddress((void**)&agg2h,  g_agg2h);
    cudaGetSymbolAddress((void**)&B1h,    g_B1h);
    cudaGetSymbolAddress((void**)&B1l,    g_B1l);
    cudaGetSymbolAddress((void**)&B2h,    g_B2h);
    cudaGetSymbolAddress((void**)&B2l,    g_B2l);

    constexpr int SMEM_L1 = 128 * 72 * 2 + 2 * 64 * (128 + 8) * 2 + 2048 * 4; // 61440
    constexpr int SMEM_L2 = 128 * 72 * 2 + 2 * 64 * (64 + 8) * 2 + 2048 * 4;  // 45056
    cudaFuncSetAttribute((const void*)wmma_layer_kernel<D_HID, 2, 4, 2, 1, true, true>,
                         cudaFuncAttributeMaxDynamicSharedMemorySize, SMEM_L1);
    cudaFuncSetAttribute((const void*)wmma_layer_kernel<D_OUT, 1, 4, 4, 2, false, false>,
                         cudaFuncAttributeMaxDynamicSharedMemorySize, SMEM_L2);

    const int nTiles = (N_NODES + 127) / 128;
    const int E4 = E / 4;   // 1e6 divisible by 4

    // 1) prep: f2h + zero cnt
    prep_kernel<<<(F2H_N4 + 255) / 256, 256>>>(
        (const float4*)x, (__half2*)xh, (int4*)cnt);

    // 2) count (+ per-edge positions), int4
    count_kernel<<<(E4 + 255) / 256, 256>>>(
        (const int4*)dst, cnt, (int4*)pos, E4);

    // 3) tile-local scan
    scan_local_kernel<<<N_TILES, SCAN_TILE>>>(cnt, rowptr, bsum, N_NODES);

    // 4) fused sums-scan + offset add
    scan_add_kernel<<<(N_NODES + 127) / 128, 128>>>(bsum, rowptr, N_NODES, E);

    // 5) atomic-free fill, int4
    fill_kernel<<<(E4 + 255) / 256, 256>>>(
        (const int4*)src, (const int4*)dst, (const int4*)pos, rowptr, csrsrc, E4);

    // 6) gather1 + weight prep (trailing 64 blocks)
    {
        const int gb = (N_NODES * (D_IN / 8) + 255) / 256;   // 3125
        const int wb = (128 * 128 + 255) / 256;              // 64
        gather_h_kernel<D_IN / 8, true><<<gb + wb, 256>>>(
            (const uint4*)xh, csrsrc, rowptr, (uint4*)agg1h, N_NODES, gb,
            w_self1, w_neigh1, B1h, B1l, w_self2, w_neigh2, B2h, B2l);
    }

    // 7) layer 1
    wmma_layer_kernel<D_HID, 2, 4, 2, 1, true, true><<<nTiles, 256, SMEM_L1>>>(
        xh, agg1h, B1h, B1l, b1, nullptr, h1h, N_NODES);

    // 8) gather 2
    gather_h_kernel<D_HID / 8, false><<<(N_NODES * (D_HID / 8) + 255) / 256, 256>>>(
        (const uint4*)h1h, csrsrc, rowptr, (uint4*)agg2h, N_NODES, 1 << 30,
        nullptr, nullptr, nullptr, nullptr, nullptr, nullptr, nullptr, nullptr);

    // 9) layer 2
    wmma_layer_kernel<D_OUT, 1, 4, 4, 2, false, false><<<nTiles, 256, SMEM_L2>>>(
        h1h, agg2h, B2h, B2l, b2, out, nullptr, N_NODES);
}

// round 17
// speedup vs baseline: 1.1029x; 1.0544x over previous
#include <cuda_runtime.h>
#include <cuda_fp16.h>
#include <mma.h>
#include <cstdint>

using namespace nvcuda;

// ---------------------------------------------------------------------------
// GraphSAGE 2-layer forward, fp16 datapath.
//   Layer 2 uses linearity: mean(h1[nb]) @ Wn2 == mean((h1 @ Wn2)[nb]).
//   layer2a computes [h1@Ws2+b2 | h1@Wn2] in one GEMM (fp32 out | fp16 z);
//   gather2add gathers the 64-wide z and adds the mean into out.
// N = 100000, E = 1e6, d_in=64, d_hid=128, d_out=64.
// ---------------------------------------------------------------------------

#define N_NODES 100000
#define E_MAX   1000000
#define D_IN    64
#define D_HID   128
#define D_OUT   64
#define SCAN_TILE 1024
#define N_TILES ((N_NODES + SCAN_TILE - 1) / SCAN_TILE)   // 98

// Scratch (device globals; no allocation allowed)
__device__ int    g_cnt   [N_NODES];
__device__ int    g_rowptr[N_NODES + 1];
__device__ int    g_bsum  [128];
__device__ int    g_pos   [E_MAX];             // per-edge within-bucket slot
__device__ int    g_csrsrc[E_MAX];
__device__ __half g_xh    [N_NODES * D_IN];    // fp16 mirror of x
__device__ __half g_h1h   [N_NODES * D_HID];   // fp16 h1 (sole copy)
__device__ __half g_agg1h [N_NODES * D_IN];    // fp16 mean-agg for layer 1
__device__ __half g_z     [N_NODES * D_OUT];   // fp16 h1@Wn2 projection
__device__ __half g_B1h[128 * 128];            // [K][N] hi(W1) fp16
__device__ __half g_B1l[128 * 128];            // lo(W1)
__device__ __half g_B2h[128 * 128];            // [K=128][N=128] hi([Ws2|Wn2])
__device__ __half g_B2l[128 * 128];            // lo([Ws2|Wn2])

// ===========================================================================
// prep: fp32->fp16 mirror of x  +  zero the count array (one launch)
// ===========================================================================
#define F2H_N4   (N_NODES * D_IN / 4)          // 400k float4
#define ZERO_N4  (N_NODES / 4)                 // 25k int4
__global__ void prep_kernel(const float4* __restrict__ x4,
                            __half2* __restrict__ xh2,
                            int4* __restrict__ cnt4) {
    int i = blockIdx.x * blockDim.x + threadIdx.x;
    if (i < F2H_N4) {
        float4 v = x4[i];
        xh2[i * 2]     = __floats2half2_rn(v.x, v.y);
        xh2[i * 2 + 1] = __floats2half2_rn(v.z, v.w);
    }
    if (i < ZERO_N4) cnt4[i] = make_int4(0, 0, 0, 0);
}

// count + per-edge position record (4 edges per thread, int4 loads)
__global__ void count_kernel(const int4* __restrict__ dst4,
                             int* __restrict__ cnt,
                             int4* __restrict__ pos4, int E4) {
    int e = blockIdx.x * blockDim.x + threadIdx.x;
    if (e < E4) {
        int4 d = dst4[e];
        int4 p;
        p.x = atomicAdd(&cnt[d.x], 1);
        p.y = atomicAdd(&cnt[d.y], 1);
        p.z = atomicAdd(&cnt[d.z], 1);
        p.w = atomicAdd(&cnt[d.w], 1);
        pos4[e] = p;
    }
}

// Phase 1: per-tile exclusive scan (coalesced), tile totals to bsum.
__global__ __launch_bounds__(SCAN_TILE)
void scan_local_kernel(const int* __restrict__ cnt,
                       int* __restrict__ local,
                       int* __restrict__ bsum, int n) {
    __shared__ int s[SCAN_TILE];
    const int tid = threadIdx.x;
    const int gid = blockIdx.x * SCAN_TILE + tid;
    int v = (gid < n) ? cnt[gid] : 0;
    s[tid] = v;
    __syncthreads();
    for (int off = 1; off < SCAN_TILE; off <<= 1) {
        int t = 0;
        if (tid >= off) t = s[tid - off];
        __syncthreads();
        if (tid >= off) s[tid] += t;
        __syncthreads();
    }
    if (gid < n) local[gid] = s[tid] - v;          // exclusive within tile
    if (tid == SCAN_TILE - 1) bsum[blockIdx.x] = s[tid];
}

// Phase 2+3 fused: every block redundantly scans the 98 tile totals in smem
// and applies its tile offset. 128 threads/block.
__global__ __launch_bounds__(128)
void scan_add_kernel(const int* __restrict__ bsum,
                     int* __restrict__ row_ptr, int n, int E) {
    __shared__ int s[128];
    __shared__ int ex[128];
    const int tid = threadIdx.x;
    int v = (tid < N_TILES) ? bsum[tid] : 0;
    s[tid] = v;
    __syncthreads();
    for (int off = 1; off < 128; off <<= 1) {
        int t = 0;
        if (tid >= off) t = s[tid - off];
        __syncthreads();
        if (tid >= off) s[tid] += t;
        __syncthreads();
    }
    ex[tid] = s[tid] - v;
    __syncthreads();
    const int gid = blockIdx.x * 128 + tid;
    const int tile = blockIdx.x >> 3;              // 8 blocks per 1024-tile
    if (gid < n) row_ptr[gid] += ex[tile];
    if (gid == 0) row_ptr[n] = E;
}

// Atomic-free fill: slot comes from the recorded per-edge position.
__global__ void fill_kernel(const int4* __restrict__ src4,
                            const int4* __restrict__ dst4,
                            const int4* __restrict__ pos4,
                            const int* __restrict__ row_ptr,
                            int* __restrict__ csr, int E4) {
    int e = blockIdx.x * blockDim.x + threadIdx.x;
    if (e < E4) {
        int4 s = src4[e];
        int4 d = dst4[e];
        int4 p = pos4[e];
        csr[row_ptr[d.x] + p.x] = s.x;
        csr[row_ptr[d.y] + p.y] = s.y;
        csr[row_ptr[d.z] + p.z] = s.z;
        csr[row_ptr[d.w] + p.w] = s.w;
    }
}

// ===========================================================================
// Weight prep items
// ===========================================================================
__device__ __forceinline__ void wprep_item(const float* ws, const float* wn,
                                           __half* Bh, __half* Bl,
                                           int DK2, int NOUT, int i) {
    int k = i / NOUT, n = i % NOUT;
    float w = (k < DK2 / 2) ? ws[k * NOUT + n] : wn[(k - DK2 / 2) * NOUT + n];
    __half hi = __float2half_rn(w);
    Bh[i] = hi;
    Bl[i] = __float2half_rn(w - __half2float(hi));
}
// layer2a combined: [K=128][N=128], cols 0-63 = Ws2, cols 64-127 = Wn2
__device__ __forceinline__ void wprep2_item(const float* ws2, const float* wn2,
                                            __half* Bh, __half* Bl, int i) {
    int k = i / 128, n = i % 128;
    float w = (n < 64) ? ws2[k * 64 + n] : wn2[k * 64 + (n - 64)];
    __half hi = __float2half_rn(w);
    Bh[i] = hi;
    Bl[i] = __float2half_rn(w - __half2float(hi));
}

// ===========================================================================
// Gather + mean over fp16 features (HADD2 pair loop). TPN threads/node.
// ADD_OUT: add the fp32 mean into out (layer-2 path); else write fp16 agg.
// Trailing blocks (WPREP) run weight prep for both layers.
// ===========================================================================
template <int TPN, bool WPREP, bool ADD_OUT>
__global__ __launch_bounds__(256)
void gather_h_kernel(const uint4* __restrict__ feat,
                     const int* __restrict__ csr,
                     const int* __restrict__ row_ptr,
                     uint4* __restrict__ aggmean_h,
                     float* __restrict__ out_add, int n,
                     int nGatherBlocks,
                     const float* __restrict__ ws1, const float* __restrict__ wn1,
                     __half* __restrict__ B1h, __half* __restrict__ B1l,
                     const float* __restrict__ ws2, const float* __restrict__ wn2,
                     __half* __restrict__ B2h, __half* __restrict__ B2l) {
    const int tid = threadIdx.x;
    if (WPREP && blockIdx.x >= nGatherBlocks) {
        int b = blockIdx.x - nGatherBlocks;
        int i = b * 256 + tid;
        if (i < 128 * 128) {
            wprep_item(ws1, wn1, B1h, B1l, 128, 128, i);
            wprep2_item(ws2, wn2, B2h, B2l, i);
        }
        return;
    }
    const int node = blockIdx.x * (256 / TPN) + tid / TPN;
    const int c = tid % TPN;
    if (node >= n) return;
    const int b = row_ptr[node];
    const int e = row_ptr[node + 1];
    float acc[8];
#pragma unroll
    for (int q = 0; q < 8; q++) acc[q] = 0.f;

    int i = b;
#pragma unroll 2
    for (; i + 1 < e; i += 2) {
        int s0 = __ldg(&csr[i]);
        int s1 = __ldg(&csr[i + 1]);
        uint4 r0 = __ldg(&feat[(size_t)s0 * TPN + c]);
        uint4 r1 = __ldg(&feat[(size_t)s1 * TPN + c]);
        const __half2* p0 = reinterpret_cast<const __half2*>(&r0);
        const __half2* p1 = reinterpret_cast<const __half2*>(&r1);
#pragma unroll
        for (int q = 0; q < 4; q++) {
            __half2 hs = __hadd2(p0[q], p1[q]);
            float2 f = __half22float2(hs);
            acc[2 * q]     += f.x;
            acc[2 * q + 1] += f.y;
        }
    }
    if (i < e) {
        int s = __ldg(&csr[i]);
        uint4 r = __ldg(&feat[(size_t)s * TPN + c]);
        const __half2* ph = reinterpret_cast<const __half2*>(&r);
#pragma unroll
        for (int q = 0; q < 4; q++) {
            float2 f = __half22float2(ph[q]);
            acc[2 * q]     += f.x;
            acc[2 * q + 1] += f.y;
        }
    }

    int d = e - b;
    float inv = 1.0f / (float)(d > 1 ? d : 1);
    if (ADD_OUT) {
        float* dst = out_add + (size_t)node * (TPN * 8) + c * 8;
        float4 a0 = *reinterpret_cast<float4*>(dst);
        float4 a1 = *reinterpret_cast<float4*>(dst + 4);
        a0.x += acc[0] * inv; a0.y += acc[1] * inv;
        a0.z += acc[2] * inv; a0.w += acc[3] * inv;
        a1.x += acc[4] * inv; a1.y += acc[5] * inv;
        a1.z += acc[6] * inv; a1.w += acc[7] * inv;
        *reinterpret_cast<float4*>(dst) = a0;
        *reinterpret_cast<float4*>(dst + 4) = a1;
    } else {
        __half2 h0 = __floats2half2_rn(acc[0] * inv, acc[1] * inv);
        __half2 h1 = __floats2half2_rn(acc[2] * inv, acc[3] * inv);
        __half2 h2 = __floats2half2_rn(acc[4] * inv, acc[5] * inv);
        __half2 h3 = __floats2half2_rn(acc[6] * inv, acc[7] * inv);
        aggmean_h[(size_t)node * TPN + c] = make_uint4(
            *(uint32_t*)&h0, *(uint32_t*)&h1, *(uint32_t*)&h2, *(uint32_t*)&h3);
    }
}

// ===========================================================================
// wmma fp16 GEMM with weight hi/lo compensation. CTA = 128 nodes x 128 cols,
// 8 warps, warp tile 32x64 (WROWS=2, WCOLS=4, COLG=2).
// MODE 1 (layer1): A chunks = xh | agg1h (both 64-wide fp16), relu, fp16 out.
// MODE 3 (layer2a): A chunks = h1h cols 0-63 | 64-127; epilogue split:
//   cols 0-63 -> fp32 out (+bias), cols 64-127 -> fp16 z (no bias, no relu).
// ===========================================================================
template <int MODE>
__global__ __launch_bounds__(256)
void wmma_layer_kernel(const __half* __restrict__ selfh,
                       const __half* __restrict__ aggh,
                       const __half* __restrict__ Bh,
                       const __half* __restrict__ Bl,
                       const float* __restrict__ bias,
                       float* __restrict__ out,
                       __half* __restrict__ outh, int nNodes) {
    constexpr int NOUT  = 128;
    constexpr int WROWS = 2, WCOLS = 4;
    constexpr int ROWU4 = (MODE == 1) ? 8 : 16;   // fp16 source row in uint4
    constexpr int ASTR  = 72;
    constexpr int BSTR  = NOUT + 8;
    constexpr int COLG  = 2;

    extern __shared__ __align__(32) char smem_raw[];
    __half* sA  = (__half*)smem_raw;                 // 128 x ASTR
    __half* sBh = sA + 128 * ASTR;                   // 64 x BSTR
    __half* sBl = sBh + 64 * BSTR;                   // 64 x BSTR
    float*  sBias = (float*)(sBl + 64 * BSTR);       // 2048 floats

    const int tid = threadIdx.x;
    const int wid = tid >> 5;
    const int lane = tid & 31;
    const int rowg = wid / COLG;
    const int colg = wid % COLG;
    const int base = blockIdx.x * 128;

    for (int i = tid; i < 16 * NOUT; i += 256) {
        int col = i % NOUT;
        float bv;
        if (MODE == 1) bv = bias[col];
        else           bv = (col < 64) ? bias[col] : 0.f;
        sBias[i] = bv;
    }
    __syncthreads();

    wmma::fragment<wmma::accumulator, 16, 16, 16, float> acc[WROWS][WCOLS];
#pragma unroll
    for (int r = 0; r < WROWS; r++)
#pragma unroll
        for (int c = 0; c < WCOLS; c++)
            wmma::load_matrix_sync(acc[r][c],
                sBias + (colg * WCOLS + c) * 16, NOUT, wmma::mem_row_major);

    for (int kc = 0; kc < 2; kc++) {
        __syncthreads();

        // ---- stage A: straight fp16 copy, 128 rows x 64 cols ----
        const uint4* src4;
        int qoff;
        if (MODE == 1) {
            src4 = reinterpret_cast<const uint4*>(kc ? aggh : selfh);
            qoff = 0;
        } else {
            src4 = reinterpret_cast<const uint4*>(selfh);
            qoff = kc * 8;
        }
#pragma unroll
        for (int jj = tid; jj < 1024; jj += 256) {
            int m = jj >> 3, c8 = jj & 7;
            int node = base + m;
            uint4 v = make_uint4(0, 0, 0, 0);
            if (node < nNodes)
                v = src4[(size_t)node * ROWU4 + qoff + c8];
            *reinterpret_cast<uint4*>(&sA[m * ASTR + c8 * 8]) = v;
        }
        // ---- stage B: 64 x 128 fp16 hi/lo ----
#pragma unroll
        for (int jj = tid; jj < 64 * NOUT / 8; jj += 256) {
            int r = jj / (NOUT / 8), c8 = jj % (NOUT / 8);
            size_t g = (size_t)(kc * 64 + r) * NOUT + c8 * 8;
            *reinterpret_cast<uint4*>(&sBh[r * BSTR + c8 * 8]) =
                *reinterpret_cast<const uint4*>(&Bh[g]);
            *reinterpret_cast<uint4*>(&sBl[r * BSTR + c8 * 8]) =
                *reinterpret_cast<const uint4*>(&Bl[g]);
        }
        __syncthreads();

        // ---- MMA over 4 k-steps of 16 ----
#pragma unroll
        for (int kk = 0; kk < 4; kk++) {
            wmma::fragment<wmma::matrix_a, 16, 16, 16, __half, wmma::row_major> a[WROWS];
#pragma unroll
            for (int r = 0; r < WROWS; r++) {
                int rr = (rowg * WROWS + r) * 16;
                wmma::load_matrix_sync(a[r], sA + rr * ASTR + kk * 16, ASTR);
            }
#pragma unroll
            for (int c = 0; c < WCOLS; c++) {
                wmma::fragment<wmma::matrix_b, 16, 16, 16, __half, wmma::row_major> bh, bl;
                int cc = (colg * WCOLS + c) * 16;
                wmma::load_matrix_sync(bh, sBh + kk * 16 * BSTR + cc, BSTR);
                wmma::load_matrix_sync(bl, sBl + kk * 16 * BSTR + cc, BSTR);
#pragma unroll
                for (int r = 0; r < WROWS; r++) {
                    wmma::mma_sync(acc[r][c], a[r], bh, acc[r][c]);
                    wmma::mma_sync(acc[r][c], a[r], bl, acc[r][c]);
                }
            }
        }
    }

    // ---- epilogue ----
    float* scratch = sBias + wid * 256;   // per-warp 16x16 fp32 tile
#pragma unroll
    for (int r = 0; r < WROWS; r++) {
        int rbase = base + (rowg * WROWS + r) * 16;
        if (rbase < nNodes) {
#pragma unroll
            for (int c = 0; c < WCOLS; c++) {
                int cc = (colg * WCOLS + c) * 16;
                if (MODE == 3 && colg == 0) {
                    // fp32 out (cols 0-63, stride 64)
                    wmma::store_matrix_sync(out + (size_t)rbase * 64 + cc,
                                            acc[r][c], 64, wmma::mem_row_major);
                } else {
                    if (MODE == 1) {
#pragma unroll
                        for (int i = 0; i < acc[r][c].num_elements; i++)
                            acc[r][c].x[i] = fmaxf(acc[r][c].x[i], 0.f);
                    }
                    // fp16 store via smem round trip
                    __syncwarp();
                    wmma::store_matrix_sync(scratch, acc[r][c], 16,
                                            wmma::mem_row_major);
                    __syncwarp();
                    int lr = lane >> 1, lc = (lane & 1) * 8;
                    float4 va = *reinterpret_cast<float4*>(&scratch[lr * 16 + lc]);
                    float4 vb = *reinterpret_cast<float4*>(&scratch[lr * 16 + lc + 4]);
                    __half2 h0 = __floats2half2_rn(va.x, va.y);
                    __half2 h1 = __floats2half2_rn(va.z, va.w);
                    __half2 h2 = __floats2half2_rn(vb.x, vb.y);
                    __half2 h3 = __floats2half2_rn(vb.z, vb.w);
                    uint4 packed = make_uint4(
                        *(uint32_t*)&h0, *(uint32_t*)&h1,
                        *(uint32_t*)&h2, *(uint32_t*)&h3);
                    if (MODE == 1) {
                        *reinterpret_cast<uint4*>(
                            &outh[(size_t)(rbase + lr) * 128 + cc + lc]) = packed;
                    } else {
                        // z (cols 64-127 -> z cols 0-63, stride 64)
                        *reinterpret_cast<uint4*>(
                            &outh[(size_t)(rbase + lr) * 64 + (cc - 64) + lc]) = packed;
                    }
                }
            }
        }
    }
}

// ===========================================================================
extern "C" void kernel_launch(void* const* d_in, const int* in_sizes, int n_in,
                              void* d_out, int out_size) {
    const float* x        = (const float*)d_in[0];
    const int*   src      = (const int*)d_in[1];
    const int*   dst      = (const int*)d_in[2];
    const float* w_self1  = (const float*)d_in[3];
    const float* w_neigh1 = (const float*)d_in[4];
    const float* b1       = (const float*)d_in[5];
    const float* w_self2  = (const float*)d_in[6];
    const float* w_neigh2 = (const float*)d_in[7];
    const float* b2       = (const float*)d_in[8];
    float* out = (float*)d_out;

    const int E = in_sizes[1];

    int *cnt, *rowptr, *bsum, *pos, *csrsrc;
    __half *xh, *h1h, *agg1h, *z;
    __half *B1h, *B1l, *B2h, *B2l;
    cudaGetSymbolAddress((void**)&cnt,    g_cnt);
    cudaGetSymbolAddress((void**)&rowptr, g_rowptr);
    cudaGetSymbolAddress((void**)&bsum,   g_bsum);
    cudaGetSymbolAddress((void**)&pos,    g_pos);
    cudaGetSymbolAddress((void**)&csrsrc, g_csrsrc);
    cudaGetSymbolAddress((void**)&xh,     g_xh);
    cudaGetSymbolAddress((void**)&h1h,    g_h1h);
    cudaGetSymbolAddress((void**)&agg1h,  g_agg1h);
    cudaGetSymbolAddress((void**)&z,      g_z);
    cudaGetSymbolAddress((void**)&B1h,    g_B1h);
    cudaGetSymbolAddress((void**)&B1l,    g_B1l);
    cudaGetSymbolAddress((void**)&B2h,    g_B2h);
    cudaGetSymbolAddress((void**)&B2l,    g_B2l);

    // smem: A (128x72 half) + B hi/lo (2 x 64 x 136 half) + 2048 floats
    constexpr int SMEM_L = 128 * 72 * 2 + 2 * 64 * 136 * 2 + 2048 * 4;  // 61440
    cudaFuncSetAttribute((const void*)wmma_layer_kernel<1>,
                         cudaFuncAttributeMaxDynamicSharedMemorySize, SMEM_L);
    cudaFuncSetAttribute((const void*)wmma_layer_kernel<3>,
                         cudaFuncAttributeMaxDynamicSharedMemorySize, SMEM_L);

    const int nTiles = (N_NODES + 127) / 128;
    const int E4 = E / 4;   // 1e6 divisible by 4

    // 1) prep: f2h + zero cnt
    prep_kernel<<<(F2H_N4 + 255) / 256, 256>>>(
        (const float4*)x, (__half2*)xh, (int4*)cnt);

    // 2) count (+ per-edge positions), int4
    count_kernel<<<(E4 + 255) / 256, 256>>>(
        (const int4*)dst, cnt, (int4*)pos, E4);

    // 3) tile-local scan
    scan_local_kernel<<<N_TILES, SCAN_TILE>>>(cnt, rowptr, bsum, N_NODES);

    // 4) fused sums-scan + offset add
    scan_add_kernel<<<(N_NODES + 127) / 128, 128>>>(bsum, rowptr, N_NODES, E);

    // 5) atomic-free fill, int4
    fill_kernel<<<(E4 + 255) / 256, 256>>>(
        (const int4*)src, (const int4*)dst, (const int4*)pos, rowptr, csrsrc, E4);

    // 6) gather1 + weight prep (trailing 64 blocks prep both B1 and B2)
    {
        const int gb = (N_NODES * (D_IN / 8) + 255) / 256;   // 3125
        const int wb = (128 * 128 + 255) / 256;              // 64
        gather_h_kernel<D_IN / 8, true, false><<<gb + wb, 256>>>(
            (const uint4*)xh, csrsrc, rowptr, (uint4*)agg1h, nullptr, N_NODES, gb,
            w_self1, w_neigh1, B1h, B1l, w_self2, w_neigh2, B2h, B2l);
    }

    // 7) layer 1: h1 = relu([xh|agg1h] @ W1 + b1)  (fp16 out)
    wmma_layer_kernel<1><<<nTiles, 256, SMEM_L>>>(
        xh, agg1h, B1h, B1l, b1, nullptr, h1h, N_NODES);

    // 8) layer 2a: out = h1@Ws2 + b2 (fp32), z = h1@Wn2 (fp16)
    wmma_layer_kernel<3><<<nTiles, 256, SMEM_L>>>(
        h1h, nullptr, B2h, B2l, b2, out, z, N_NODES);

    // 9) gather2add: out += mean(z[nb])   (64-wide gather)
    gather_h_kernel<D_OUT / 8, false, true>
        <<<(N_NODES * (D_OUT / 8) + 255) / 256, 256>>>(
        (const uint4*)z, csrsrc, rowptr, nullptr, out, N_NODES, 1 << 30,
        nullptr, nullptr, nullptr, nullptr, nullptr, nullptr, nullptr, nullptr);
}